// round 9
// baseline (speedup 1.0000x reference)
#include <cuda_runtime.h>
#include <math_constants.h>

// Batched nearest-neighbor argmin + gather (HBM-streaming).
//   y: [B,2] f32, Y_surf: [B,2,G] f32, U_grid: [2,G] f32, out: [B,2] f32
//   out[b,:] = U_grid[:, argmin_g ||Y_surf[b,:,g] - y[b,:]||^2]
//
// Persistent + contiguous chunks (R4) FIXED with software pipelining:
// before the per-sample reduction, issue the first x2 load batch of the
// NEXT sample. LDGs proceed across __syncthreads (BAR drains STS only),
// so DRAM stays fed through every epilogue — removing R4's ~4% dead time.
// Inner loop/accumulators/u64 tail identical to R6 (best measured config).

#define NT 128

struct Acc { float d[4]; int g[4]; };

__device__ __forceinline__ void proc4(const float4& a, const float4& c, int g,
                                      float y0, float y1, Acc& acc) {
    float dx, dz, d;
    dx = a.x - y0; dz = c.x - y1; d = dx * dx + dz * dz;
    if (d < acc.d[0]) { acc.d[0] = d; acc.g[0] = g + 0; }
    dx = a.y - y0; dz = c.y - y1; d = dx * dx + dz * dz;
    if (d < acc.d[1]) { acc.d[1] = d; acc.g[1] = g + 1; }
    dx = a.z - y0; dz = c.z - y1; d = dx * dx + dz * dz;
    if (d < acc.d[2]) { acc.d[2] = d; acc.g[2] = g + 2; }
    dx = a.w - y0; dz = c.w - y1; d = dx * dx + dz * dz;
    if (d < acc.d[3]) { acc.d[3] = d; acc.g[3] = g + 3; }
}

__device__ __forceinline__ unsigned long long pack(float d, int g) {
    return ((unsigned long long)__float_as_uint(d) << 32) | (unsigned)g;
}

__global__ __launch_bounds__(NT)
void lqr_argmin_pipe_kernel(const float* __restrict__ y,
                            const float* __restrict__ Ys,
                            const float* __restrict__ Ug,
                            float* __restrict__ out,
                            int B, int G) {
    const int tid = threadIdx.x;
    const int w   = tid >> 5;
    __shared__ unsigned long long sb[NT / 32];

    // Contiguous chunk per CTA.
    const int nCta = gridDim.x;
    const int q = B / nCta, r = B % nCta;
    const int cta = blockIdx.x;
    const int b0 = cta * q + min(cta, r);
    const int b1 = b0 + q + (cta < r ? 1 : 0);

    const int n4 = G >> 2;  // G % 4 == 0 (G = 2500 -> 625); n4 > 2*NT assumed
                            // for the pipelined prologue (true here: 625 > 256)

    // Prologue: prefetch batch0 (indices tid, tid+NT) of first sample.
    float4 pa0, pa1, pc0, pc1;
    if (b0 < b1) {
        const float4* __restrict__ v0 =
            reinterpret_cast<const float4*>(Ys + (size_t)b0 * 2 * G);
        const float4* __restrict__ v1 = v0 + n4;
        pa0 = v0[tid]; pa1 = v0[tid + NT];
        pc0 = v1[tid]; pc1 = v1[tid + NT];
    }

    for (int b = b0; b < b1; ++b) {
        const float y0 = y[2 * b + 0];
        const float y1 = y[2 * b + 1];

        const float4* __restrict__ v0 =
            reinterpret_cast<const float4*>(Ys + (size_t)b * 2 * G);
        const float4* __restrict__ v1 = v0 + n4;

        Acc acc;
        #pragma unroll
        for (int k = 0; k < 4; k++) { acc.d[k] = CUDART_INF_F; acc.g[k] = 0; }

        // Consume prefetched batch0.
        proc4(pa0, pc0, tid << 2,        y0, y1, acc);
        proc4(pa1, pc1, (tid + NT) << 2, y0, y1, acc);

        // Remaining batches (x2 unroll, MLP_p1=4).
        int i = tid + 2 * NT;
        for (; i + NT < n4; i += 2 * NT) {
            float4 a0 = v0[i];
            float4 a1 = v0[i + NT];
            float4 c0 = v1[i];
            float4 c1 = v1[i + NT];
            proc4(a0, c0, i << 2,        y0, y1, acc);
            proc4(a1, c1, (i + NT) << 2, y0, y1, acc);
        }
        if (i < n4) {
            float4 a = v0[i];
            float4 c = v1[i];
            proc4(a, c, i << 2, y0, y1, acc);
        }

        // Prefetch batch0 of NEXT sample before the reduction: keeps DRAM
        // busy through the epilogue (loads complete across the barriers).
        if (b + 1 < b1) {
            const float4* __restrict__ w0 = v0 + 2 * n4;
            const float4* __restrict__ w1 = w0 + n4;
            pa0 = w0[tid]; pa1 = w0[tid + NT];
            pc0 = w1[tid]; pc1 = w1[tid + NT];
        }

        // Packed u64 min == (min d2, tie -> min idx); exact jnp.argmin.
        unsigned long long best = pack(acc.d[0], acc.g[0]);
        #pragma unroll
        for (int k = 1; k < 4; k++) {
            unsigned long long o = pack(acc.d[k], acc.g[k]);
            if (o < best) best = o;
        }
        #pragma unroll
        for (int off = 16; off > 0; off >>= 1) {
            unsigned long long o = __shfl_down_sync(0xffffffffu, best, off);
            if (o < best) best = o;
        }

        if ((tid & 31) == 0) sb[w] = best;
        __syncthreads();

        if (w == 0) {
            const int nw = NT / 32;
            best = (tid < nw) ? sb[tid] : 0xffffffffffffffffULL;
            #pragma unroll
            for (int off = 16; off > 0; off >>= 1) {
                unsigned long long o = __shfl_down_sync(0xffffffffu, best, off);
                if (o < best) best = o;
            }
            if (tid == 0) {
                const int bidx = (int)(unsigned)best;
                out[2 * b + 0] = Ug[bidx];
                out[2 * b + 1] = Ug[(size_t)G + bidx];
            }
        }
        __syncthreads();  // protect sb reuse next sample
    }
}

extern "C" void kernel_launch(void* const* d_in, const int* in_sizes, int n_in,
                              void* d_out, int out_size) {
    const float* y  = (const float*)d_in[0];   // [B, 2]
    const float* Ys = (const float*)d_in[1];   // [B, 2, G]
    const float* Ug = (const float*)d_in[2];   // [2, G]
    float* out = (float*)d_out;                // [B, 2]

    const int B = in_sizes[0] / 2;
    const int G = in_sizes[2] / 2;

    int dev = 0;
    cudaGetDevice(&dev);
    int numSM = 148;
    cudaDeviceGetAttribute(&numSM, cudaDevAttrMultiProcessorCount, dev);
    int maxB = 8;
    cudaOccupancyMaxActiveBlocksPerMultiprocessor(&maxB, lqr_argmin_pipe_kernel,
                                                  NT, 0);
    int grid = numSM * maxB;
    if (grid > B) grid = B;
    if (grid < 1) grid = 1;

    lqr_argmin_pipe_kernel<<<grid, NT>>>(y, Ys, Ug, out, B, G);
}

// round 10
// speedup vs baseline: 1.0653x; 1.0653x over previous
#include <cuda_runtime.h>
#include <math_constants.h>
#include <cstdint>

// Batched nearest-neighbor argmin + gather (HBM-streaming).
//   y: [B,2] f32, Y_surf: [B,2,G] f32, U_grid: [2,G] f32, out: [B,2] f32
//   out[b,:] = U_grid[:, argmin_g ||Y_surf[b,:,g] - y[b,:]||^2]
//
// Block-per-sample + TMA bulk: one cp.async.bulk of the whole 2*G*4-byte
// sample (contiguous 20KB DRAM request -> max row locality, zero LDG queue
// pressure), compute from smem with R6's x2 loop + 4 independent argmin
// accumulators + packed-u64 reduction (exact jnp.argmin tie-break).
// Falls back to the pure-LDG R6 kernel if alignment/size preconditions fail.

#define NT 128

struct Acc { float d[4]; int g[4]; };

__device__ __forceinline__ void proc4(const float4& a, const float4& c, int g,
                                      float y0, float y1, Acc& acc) {
    float dx, dz, d;
    dx = a.x - y0; dz = c.x - y1; d = dx * dx + dz * dz;
    if (d < acc.d[0]) { acc.d[0] = d; acc.g[0] = g + 0; }
    dx = a.y - y0; dz = c.y - y1; d = dx * dx + dz * dz;
    if (d < acc.d[1]) { acc.d[1] = d; acc.g[1] = g + 1; }
    dx = a.z - y0; dz = c.z - y1; d = dx * dx + dz * dz;
    if (d < acc.d[2]) { acc.d[2] = d; acc.g[2] = g + 2; }
    dx = a.w - y0; dz = c.w - y1; d = dx * dx + dz * dz;
    if (d < acc.d[3]) { acc.d[3] = d; acc.g[3] = g + 3; }
}

__device__ __forceinline__ unsigned long long pack(float d, int g) {
    return ((unsigned long long)__float_as_uint(d) << 32) | (unsigned)g;
}

__device__ __forceinline__ unsigned long long block_reduce_min(
    unsigned long long best, int tid, unsigned long long* sb) {
    #pragma unroll
    for (int off = 16; off > 0; off >>= 1) {
        unsigned long long o = __shfl_down_sync(0xffffffffu, best, off);
        if (o < best) best = o;
    }
    const int w = tid >> 5;
    if ((tid & 31) == 0) sb[w] = best;
    __syncthreads();
    if (w == 0) {
        const int nw = NT / 32;
        best = (tid < nw) ? sb[tid] : 0xffffffffffffffffULL;
        #pragma unroll
        for (int off = 16; off > 0; off >>= 1) {
            unsigned long long o = __shfl_down_sync(0xffffffffu, best, off);
            if (o < best) best = o;
        }
    }
    return best;
}

__global__ __launch_bounds__(NT)
void lqr_argmin_tma_kernel(const float* __restrict__ y,
                           const float* __restrict__ Ys,
                           const float* __restrict__ Ug,
                           float* __restrict__ out,
                           int G) {
    extern __shared__ unsigned char dsm[];   // [0,8) mbar | [16, 16+2*G*4) tile
    __shared__ unsigned long long sb[NT / 32];

    const int b   = blockIdx.x;
    const int tid = threadIdx.x;
    const unsigned tile_bytes = 2u * (unsigned)G * 4u;

    uint32_t smem_u32;
    asm("{ .reg .u64 t; cvta.to.shared.u64 t, %1; cvt.u32.u64 %0, t; }"
        : "=r"(smem_u32) : "l"(dsm));
    const uint32_t mbar_addr = smem_u32;
    const uint32_t tile_addr = smem_u32 + 16;

    if (tid == 0) {
        asm volatile("mbarrier.init.shared.b64 [%0], 1;"
                     :: "r"(mbar_addr) : "memory");
    }
    __syncthreads();

    if (tid == 0) {
        asm volatile("mbarrier.arrive.expect_tx.shared.b64 _, [%0], %1;"
                     :: "r"(mbar_addr), "r"(tile_bytes) : "memory");
        const float* src = Ys + (size_t)b * 2 * G;
        asm volatile(
            "cp.async.bulk.shared::cluster.global.mbarrier::complete_tx::bytes "
            "[%0], [%1], %2, [%3];"
            :: "r"(tile_addr), "l"(src), "r"(tile_bytes), "r"(mbar_addr)
            : "memory");
    }

    // Wait for the bulk copy (parity 0; barrier used exactly once).
    {
        uint32_t done;
        asm volatile(
            "{\n\t"
            ".reg .pred p;\n\t"
            "mbarrier.try_wait.parity.acquire.cta.shared::cta.b64 p, [%1], 0;\n\t"
            "selp.b32 %0, 1, 0, p;\n\t"
            "}" : "=r"(done) : "r"(mbar_addr) : "memory");
        if (!done) {
            asm volatile(
                "{\n\t"
                ".reg .pred P1;\n\t"
                "W_%=:\n\t"
                "mbarrier.try_wait.parity.acquire.cta.shared::cta.b64 P1, [%0], 0, 0x989680;\n\t"
                "@P1 bra.uni D_%=;\n\t"
                "bra.uni W_%=;\n\t"
                "D_%=:\n\t"
                "}" :: "r"(mbar_addr) : "memory");
        }
    }

    const float y0 = y[2 * b + 0];
    const float y1 = y[2 * b + 1];

    const float4* __restrict__ v0 =
        reinterpret_cast<const float4*>(dsm + 16);
    const float4* __restrict__ v1 = v0 + (G >> 2);
    const int n4 = G >> 2;  // G % 4 == 0 (G = 2500)

    Acc acc;
    #pragma unroll
    for (int k = 0; k < 4; k++) { acc.d[k] = CUDART_INF_F; acc.g[k] = 0; }

    int i = tid;
    for (; i + NT < n4; i += 2 * NT) {
        float4 a0 = v0[i];
        float4 a1 = v0[i + NT];
        float4 c0 = v1[i];
        float4 c1 = v1[i + NT];
        proc4(a0, c0, i << 2,        y0, y1, acc);
        proc4(a1, c1, (i + NT) << 2, y0, y1, acc);
    }
    if (i < n4) {
        float4 a = v0[i];
        float4 c = v1[i];
        proc4(a, c, i << 2, y0, y1, acc);
    }

    unsigned long long best = pack(acc.d[0], acc.g[0]);
    #pragma unroll
    for (int k = 1; k < 4; k++) {
        unsigned long long o = pack(acc.d[k], acc.g[k]);
        if (o < best) best = o;
    }

    best = block_reduce_min(best, tid, sb);
    if (tid == 0) {
        const int bidx = (int)(unsigned)best;
        out[2 * b + 0] = Ug[bidx];
        out[2 * b + 1] = Ug[(size_t)G + bidx];
    }
}

// Fallback: R6 pure-LDG kernel (used if TMA preconditions fail).
__global__ __launch_bounds__(NT)
void lqr_argmin_ldg_kernel(const float* __restrict__ y,
                           const float* __restrict__ Ys,
                           const float* __restrict__ Ug,
                           float* __restrict__ out,
                           int G) {
    __shared__ unsigned long long sb[NT / 32];
    const int b   = blockIdx.x;
    const int tid = threadIdx.x;

    const float y0 = y[2 * b + 0];
    const float y1 = y[2 * b + 1];

    const float* r0 = Ys + (size_t)b * 2 * G;
    const float* r1 = r0 + G;

    float bd = CUDART_INF_F;
    int   bg = 0;
    for (int g = tid; g < G; g += NT) {
        float dx = r0[g] - y0;
        float dz = r1[g] - y1;
        float d = dx * dx + dz * dz;
        if (d < bd) { bd = d; bg = g; }
    }
    unsigned long long best = pack(bd, bg);
    best = block_reduce_min(best, tid, sb);
    if (tid == 0) {
        const int bidx = (int)(unsigned)best;
        out[2 * b + 0] = Ug[bidx];
        out[2 * b + 1] = Ug[(size_t)G + bidx];
    }
}

extern "C" void kernel_launch(void* const* d_in, const int* in_sizes, int n_in,
                              void* d_out, int out_size) {
    const float* y  = (const float*)d_in[0];   // [B, 2]
    const float* Ys = (const float*)d_in[1];   // [B, 2, G]
    const float* Ug = (const float*)d_in[2];   // [2, G]
    float* out = (float*)d_out;                // [B, 2]

    const int B = in_sizes[0] / 2;
    const int G = in_sizes[2] / 2;

    const size_t row_bytes = (size_t)2 * G * 4;
    const bool tma_ok = ((G & 3) == 0) && (row_bytes % 16 == 0) &&
                        ((uintptr_t)Ys % 16 == 0) && (row_bytes <= 200000);

    if (tma_ok) {
        const int smem = 16 + (int)row_bytes;
        lqr_argmin_tma_kernel<<<B, NT, smem>>>(y, Ys, Ug, out, G);
    } else {
        lqr_argmin_ldg_kernel<<<B, NT>>>(y, Ys, Ug, out, G);
    }
}